// round 2
// baseline (speedup 1.0000x reference)
#include <cuda_runtime.h>

#define NN    4096
#define CC    64
#define HH    128
#define BSDIM 48
#define NCOL  (BSDIM * HH)   // 6144
#define KDIM  NN

#define BM 128
#define BN 128
#define BK 16

// Scratch (allocation-free contract: __device__ globals)
__device__ float g_d[NN];
__device__ float g_Y[(size_t)NN * NCOL];   // ~100 MB: Y[j, bs*H + h] = d_j * x_emb[bs,j,h]

// ---------------------------------------------------------------------------
// Kernel 1: d[i] = rsqrt(rowsum(A[i,:]) + 1)
// ---------------------------------------------------------------------------
__global__ void rowsum_kernel(const float* __restrict__ A) {
    int row = blockIdx.x;
    const float* a = A + (size_t)row * NN;
    float s = 0.f;
    for (int j = threadIdx.x; j < NN; j += blockDim.x) s += a[j];
    __shared__ float red[32];
    #pragma unroll
    for (int o = 16; o > 0; o >>= 1) s += __shfl_down_sync(0xffffffffu, s, o);
    if ((threadIdx.x & 31) == 0) red[threadIdx.x >> 5] = s;
    __syncthreads();
    if (threadIdx.x < 32) {
        float v = (threadIdx.x < (blockDim.x >> 5)) ? red[threadIdx.x] : 0.f;
        #pragma unroll
        for (int o = 16; o > 0; o >>= 1) v += __shfl_down_sync(0xffffffffu, v, o);
        if (threadIdx.x == 0) g_d[row] = rsqrtf(v + 1.0f);
    }
}

// ---------------------------------------------------------------------------
// Kernel 2: Y[j, bs*128+h] = d_j * sum_c x[bs,j,c] * W[h,c]
// grid = (NN/16, BSDIM), block = 256
// ---------------------------------------------------------------------------
__global__ __launch_bounds__(256) void embed_kernel(const float* __restrict__ x,
                                                    const float* __restrict__ W) {
    __shared__ float Ws[HH * 65];   // pad 64->65 to kill bank conflicts
    __shared__ float xs[16 * CC];
    int bs  = blockIdx.y;
    int jt  = blockIdx.x;           // 16 j-rows per block
    int tid = threadIdx.x;

    for (int idx = tid; idx < HH * CC; idx += 256) {
        int h = idx >> 6, c = idx & 63;
        Ws[h * 65 + c] = W[idx];
    }
    for (int idx = tid; idx < 16 * CC; idx += 256) {
        xs[idx] = x[((size_t)bs * NN + jt * 16) * CC + idx];
    }
    __syncthreads();

    int h  = tid & 127;
    int j0 = (tid >> 7) * 8;
    float acc[8] = {0.f, 0.f, 0.f, 0.f, 0.f, 0.f, 0.f, 0.f};
    #pragma unroll 8
    for (int c = 0; c < CC; c++) {
        float w = Ws[h * 65 + c];
        #pragma unroll
        for (int jj = 0; jj < 8; jj++)
            acc[jj] += xs[(j0 + jj) * CC + c] * w;
    }
    #pragma unroll
    for (int jj = 0; jj < 8; jj++) {
        int j = jt * 16 + j0 + jj;
        g_Y[(size_t)j * NCOL + bs * HH + h] = g_d[j] * acc[jj];
    }
}

// ---------------------------------------------------------------------------
// Kernel 3: Z = A @ Y, fused epilogue out = sigmoid(Y/d_i - d_i*Z)
// grid = (BSDIM, NN/BM), block = 256, 8x8 per-thread tile
// ---------------------------------------------------------------------------
__global__ __launch_bounds__(256, 2) void gemm_kernel(const float* __restrict__ A,
                                                      float* __restrict__ out) {
    __shared__ float As[BK][BM];        // transposed A tile
    __shared__ float Bs[BK][BN + 4];    // padded

    int tid     = threadIdx.x;
    int bs      = blockIdx.x;           // one column tile == one (b,s)
    int rowBase = blockIdx.y * BM;
    int colBase = bs * BN;

    int tx = tid & 15;                  // N direction
    int ty = tid >> 4;                  // M direction

    float acc[8][8];
    #pragma unroll
    for (int i = 0; i < 8; i++)
        #pragma unroll
        for (int j = 0; j < 8; j++) acc[i][j] = 0.f;

    float4 aReg[2], bReg[2];

    // preload tile 0
    #pragma unroll
    for (int it = 0; it < 2; it++) {
        int lin = tid + it * 256;
        int r   = lin >> 2;             // 0..127
        int kq  = (lin & 3) * 4;        // 0,4,8,12
        float4 v = *reinterpret_cast<const float4*>(&A[(size_t)(rowBase + r) * KDIM + kq]);
        As[kq + 0][r] = v.x; As[kq + 1][r] = v.y; As[kq + 2][r] = v.z; As[kq + 3][r] = v.w;
        int lr = lin >> 5;              // 0..15
        int lc = (lin & 31) * 4;        // 0..124
        *reinterpret_cast<float4*>(&Bs[lr][lc]) =
            *reinterpret_cast<const float4*>(&g_Y[(size_t)lr * NCOL + colBase + lc]);
    }
    __syncthreads();

    for (int kt = 0; kt < KDIM / BK; kt++) {
        // prefetch next tile into registers
        if (kt + 1 < KDIM / BK) {
            int k0 = (kt + 1) * BK;
            #pragma unroll
            for (int it = 0; it < 2; it++) {
                int lin = tid + it * 256;
                int r   = lin >> 2;
                int kq  = (lin & 3) * 4;
                aReg[it] = *reinterpret_cast<const float4*>(&A[(size_t)(rowBase + r) * KDIM + k0 + kq]);
                int lr = lin >> 5;
                int lc = (lin & 31) * 4;
                bReg[it] = *reinterpret_cast<const float4*>(&g_Y[(size_t)(k0 + lr) * NCOL + colBase + lc]);
            }
        }
        #pragma unroll
        for (int kk = 0; kk < BK; kk++) {
            float a[8], b[8];
            #pragma unroll
            for (int j = 0; j < 8; j++) a[j] = As[kk][ty * 8 + j];
            #pragma unroll
            for (int j = 0; j < 8; j++) b[j] = Bs[kk][tx * 8 + j];
            #pragma unroll
            for (int i = 0; i < 8; i++)
                #pragma unroll
                for (int j = 0; j < 8; j++)
                    acc[i][j] += a[i] * b[j];
        }
        __syncthreads();
        if (kt + 1 < KDIM / BK) {
            #pragma unroll
            for (int it = 0; it < 2; it++) {
                int lin = tid + it * 256;
                int r   = lin >> 2;
                int kq  = (lin & 3) * 4;
                As[kq + 0][r] = aReg[it].x; As[kq + 1][r] = aReg[it].y;
                As[kq + 2][r] = aReg[it].z; As[kq + 3][r] = aReg[it].w;
                int lr = lin >> 5;
                int lc = (lin & 31) * 4;
                *reinterpret_cast<float4*>(&Bs[lr][lc]) = bReg[it];
            }
            __syncthreads();
        }
    }

    // epilogue: out[bs, row, h] = sigmoid(Y[row,col]/d_row - d_row * Z)
    #pragma unroll
    for (int i = 0; i < 8; i++) {
        int row = rowBase + ty * 8 + i;
        float di  = g_d[row];
        float inv = 1.0f / di;
        #pragma unroll
        for (int j = 0; j < 8; j++) {
            int h   = tx * 8 + j;
            float yv = g_Y[(size_t)row * NCOL + colBase + h];
            float v  = yv * inv - di * acc[i][j];
            out[((size_t)bs * NN + row) * HH + h] = 1.0f / (1.0f + __expf(-v));
        }
    }
}

// ---------------------------------------------------------------------------
// Kernel 4: copy A into second output slot
// ---------------------------------------------------------------------------
__global__ void copyA_kernel(const float* __restrict__ A, float* __restrict__ dst) {
    size_t i = (size_t)blockIdx.x * blockDim.x + threadIdx.x;
    size_t n4 = (size_t)NN * NN / 4;
    const float4* src = reinterpret_cast<const float4*>(A);
    float4* d = reinterpret_cast<float4*>(dst);
    for (; i < n4; i += (size_t)gridDim.x * blockDim.x) d[i] = src[i];
}

// ---------------------------------------------------------------------------
extern "C" void kernel_launch(void* const* d_in, const int* in_sizes, int n_in,
                              void* d_out, int out_size) {
    const float* x = (const float*)d_in[0];   // [4,12,4096,64]
    const float* A = (const float*)d_in[1];   // [4096,4096]
    const float* W = (const float*)d_in[2];   // [128,64]
    float* out = (float*)d_out;               // out [48*4096*128] then A [4096*4096]

    rowsum_kernel<<<NN, 256>>>(A);
    embed_kernel<<<dim3(NN / 16, BSDIM), 256>>>(x, W);
    gemm_kernel<<<dim3(BSDIM, NN / BM), 256>>>(A, out);
    copyA_kernel<<<2048, 256>>>(A, out + (size_t)BSDIM * NN * HH);
}

// round 3
// speedup vs baseline: 7.4452x; 7.4452x over previous
#include <cuda_runtime.h>
#include <cuda_bf16.h>
#include <cstdint>

#define NN    4096
#define CC    64
#define HH    128
#define BSDIM 48
#define NCOL  (BSDIM * CC)    // 3072  (C-space columns)

// ---------------- scratch (__device__ globals; allocation-free) -------------
__device__ float         g_d[NN];
__device__ __nv_bfloat16 g_Abf[(size_t)NN * NN];       // 33.5 MB
__device__ __nv_bfloat16 g_XdT[(size_t)NCOL * NN];     // 25 MB  [col][j], K-major
__device__ float         g_U[(size_t)NN * NCOL];       // 50 MB  [i][col]

// ---------------------------------------------------------------------------
// K1: d[i] = rsqrt(rowsum(A[i,:]) + 1)
// ---------------------------------------------------------------------------
__global__ void rowsum_kernel(const float* __restrict__ A) {
    int row = blockIdx.x;
    const float* a = A + (size_t)row * NN;
    float s = 0.f;
    for (int j = threadIdx.x; j < NN; j += blockDim.x) s += a[j];
    __shared__ float red[32];
    #pragma unroll
    for (int o = 16; o > 0; o >>= 1) s += __shfl_down_sync(0xffffffffu, s, o);
    if ((threadIdx.x & 31) == 0) red[threadIdx.x >> 5] = s;
    __syncthreads();
    if (threadIdx.x < 32) {
        float v = (threadIdx.x < (blockDim.x >> 5)) ? red[threadIdx.x] : 0.f;
        #pragma unroll
        for (int o = 16; o > 0; o >>= 1) v += __shfl_down_sync(0xffffffffu, v, o);
        if (threadIdx.x == 0) g_d[row] = rsqrtf(v + 1.0f);
    }
}

// ---------------------------------------------------------------------------
// K2a: A -> bf16
// ---------------------------------------------------------------------------
__global__ void convA_kernel(const float* __restrict__ A) {
    size_t i  = (size_t)blockIdx.x * blockDim.x + threadIdx.x;
    size_t n4 = (size_t)NN * NN / 4;
    const float4* A4 = reinterpret_cast<const float4*>(A);
    __nv_bfloat162* o2 = reinterpret_cast<__nv_bfloat162*>(g_Abf);
    for (; i < n4; i += (size_t)gridDim.x * blockDim.x) {
        float4 v = A4[i];
        o2[2 * i]     = __floats2bfloat162_rn(v.x, v.y);
        o2[2 * i + 1] = __floats2bfloat162_rn(v.z, v.w);
    }
}

// ---------------------------------------------------------------------------
// K2b: XdT[bs*64+c][j] = bf16(d_j * x[bs,j,c])   (transpose via smem tile)
// grid = (NN/64, BSDIM)
// ---------------------------------------------------------------------------
__global__ __launch_bounds__(256) void build_xdt_kernel(const float* __restrict__ x) {
    __shared__ float ts[64 * 65];
    int bs = blockIdx.y, j0 = blockIdx.x * 64, tid = threadIdx.x;
    const float* xb = x + ((size_t)bs * NN + j0) * CC;
    for (int idx = tid; idx < 64 * CC; idx += 256)
        ts[(idx >> 6) * 65 + (idx & 63)] = xb[idx];
    __syncthreads();
    for (int idx = tid; idx < 64 * CC; idx += 256) {
        int c = idx >> 6, jj = idx & 63;
        int j = j0 + jj;
        g_XdT[((size_t)bs * CC + c) * NN + j] = __float2bfloat16(g_d[j] * ts[jj * 65 + c]);
    }
}

// ---------------------------------------------------------------------------
// K3: U = Abf @ XdT^T  (bf16 mma.sync, fp32 accum)
// BM=128, BN=128, BK=32, 256 thr, 8 warps (2M x 4N), warp tile 64x32
// grid = (NCOL/128=24, NN/128=32)
// ---------------------------------------------------------------------------
__global__ __launch_bounds__(256, 2) void gemm_bf16_kernel() {
    __shared__ __align__(16) __nv_bfloat16 sA[2][128][40];
    __shared__ __align__(16) __nv_bfloat16 sB[2][128][40];

    int tid = threadIdx.x;
    int rowBase = blockIdx.y * 128;
    int colBase = blockIdx.x * 128;
    int warp = tid >> 5, lane = tid & 31;
    int wm = warp & 1, wn = warp >> 1;

    float acc[4][4][4];
    #pragma unroll
    for (int a = 0; a < 4; a++)
        #pragma unroll
        for (int b = 0; b < 4; b++)
            #pragma unroll
            for (int c = 0; c < 4; c++) acc[a][b][c] = 0.f;

    auto load_stage = [&](int s, int kt) {
        #pragma unroll
        for (int it = 0; it < 2; it++) {
            int lin = tid + it * 256;
            int r = lin >> 2, q = lin & 3;
            const __nv_bfloat16* ga = g_Abf + ((size_t)(rowBase + r)) * NN + kt * 32 + q * 8;
            uint32_t da = (uint32_t)__cvta_generic_to_shared(&sA[s][r][q * 8]);
            asm volatile("cp.async.cg.shared.global [%0],[%1],16;\n" :: "r"(da), "l"(ga));
            const __nv_bfloat16* gb = g_XdT + ((size_t)(colBase + r)) * NN + kt * 32 + q * 8;
            uint32_t db = (uint32_t)__cvta_generic_to_shared(&sB[s][r][q * 8]);
            asm volatile("cp.async.cg.shared.global [%0],[%1],16;\n" :: "r"(db), "l"(gb));
        }
        asm volatile("cp.async.commit_group;\n" ::);
    };

    load_stage(0, 0);

    const int KT = NN / 32;   // 128
    for (int kt = 0; kt < KT; kt++) {
        int s = kt & 1;
        if (kt + 1 < KT) {
            load_stage(s ^ 1, kt + 1);
            asm volatile("cp.async.wait_group 1;\n" ::);
        } else {
            asm volatile("cp.async.wait_group 0;\n" ::);
        }
        __syncthreads();

        #pragma unroll
        for (int kk = 0; kk < 2; kk++) {
            uint32_t a[4][4], b[2][4];
            #pragma unroll
            for (int mi = 0; mi < 4; mi++) {
                uint32_t addr = (uint32_t)__cvta_generic_to_shared(
                    &sA[s][wm * 64 + mi * 16 + (lane & 15)][kk * 16 + (lane >> 4) * 8]);
                asm volatile("ldmatrix.sync.aligned.m8n8.x4.shared.b16 {%0,%1,%2,%3},[%4];\n"
                    : "=r"(a[mi][0]), "=r"(a[mi][1]), "=r"(a[mi][2]), "=r"(a[mi][3]) : "r"(addr));
            }
            #pragma unroll
            for (int nj = 0; nj < 2; nj++) {
                uint32_t addr = (uint32_t)__cvta_generic_to_shared(
                    &sB[s][wn * 32 + nj * 16 + (lane & 15)][kk * 16 + (lane >> 4) * 8]);
                asm volatile("ldmatrix.sync.aligned.m8n8.x4.shared.b16 {%0,%1,%2,%3},[%4];\n"
                    : "=r"(b[nj][0]), "=r"(b[nj][1]), "=r"(b[nj][2]), "=r"(b[nj][3]) : "r"(addr));
            }
            #pragma unroll
            for (int mi = 0; mi < 4; mi++) {
                #pragma unroll
                for (int nj = 0; nj < 2; nj++) {
                    asm volatile(
                        "mma.sync.aligned.m16n8k16.row.col.f32.bf16.bf16.f32 "
                        "{%0,%1,%2,%3},{%4,%5,%6,%7},{%8,%9},{%0,%1,%2,%3};\n"
                        : "+f"(acc[mi][nj*2][0]), "+f"(acc[mi][nj*2][1]),
                          "+f"(acc[mi][nj*2][2]), "+f"(acc[mi][nj*2][3])
                        : "r"(a[mi][0]), "r"(a[mi][1]), "r"(a[mi][2]), "r"(a[mi][3]),
                          "r"(b[nj][0]), "r"(b[nj][2]));
                    asm volatile(
                        "mma.sync.aligned.m16n8k16.row.col.f32.bf16.bf16.f32 "
                        "{%0,%1,%2,%3},{%4,%5,%6,%7},{%8,%9},{%0,%1,%2,%3};\n"
                        : "+f"(acc[mi][nj*2+1][0]), "+f"(acc[mi][nj*2+1][1]),
                          "+f"(acc[mi][nj*2+1][2]), "+f"(acc[mi][nj*2+1][3])
                        : "r"(a[mi][0]), "r"(a[mi][1]), "r"(a[mi][2]), "r"(a[mi][3]),
                          "r"(b[nj][1]), "r"(b[nj][3]));
                }
            }
        }
        __syncthreads();
    }

    // store U (fp32)
    #pragma unroll
    for (int mi = 0; mi < 4; mi++) {
        int r0 = rowBase + wm * 64 + mi * 16 + (lane >> 2);
        #pragma unroll
        for (int nf = 0; nf < 4; nf++) {
            int c = colBase + wn * 32 + (nf >> 1) * 16 + (nf & 1) * 8 + (lane & 3) * 2;
            float2 v0 = make_float2(acc[mi][nf][0], acc[mi][nf][1]);
            *reinterpret_cast<float2*>(&g_U[(size_t)r0 * NCOL + c]) = v0;
            float2 v1 = make_float2(acc[mi][nf][2], acc[mi][nf][3]);
            *reinterpret_cast<float2*>(&g_U[(size_t)(r0 + 8) * NCOL + c]) = v1;
        }
    }
}

// ---------------------------------------------------------------------------
// K4: out = sigmoid( (x - d*U) @ W^T )  via tf32 mma m16n8k8
// tile: 32 rows x 128 h, K=64; 256 thr, 8 warps (2M x 4N), warp 16x32
// grid = BSDIM*NN/32 = 6144
// ---------------------------------------------------------------------------
__global__ __launch_bounds__(256) void epilogue_kernel(const float* __restrict__ x,
                                                       const float* __restrict__ W,
                                                       float* __restrict__ out) {
    __shared__ float sW[HH * 68];
    __shared__ float sV[32 * 68];
    int tid = threadIdx.x;
    int r0  = blockIdx.x * 32;          // flattened (bs,i) row
    int bs  = r0 >> 12;                 // never straddles a bs boundary

    for (int idx = tid; idx < HH * CC; idx += 256) {
        int h = idx >> 6, c = idx & 63;
        sW[h * 68 + c] = W[idx];
    }
    for (int idx = tid; idx < 32 * CC; idx += 256) {
        int lr = idx >> 6, c = idx & 63;
        int gr = r0 + lr;
        int i  = gr & (NN - 1);
        sV[lr * 68 + c] = x[(size_t)gr * CC + c]
                        - g_d[i] * g_U[(size_t)i * NCOL + bs * CC + c];
    }
    __syncthreads();

    int warp = tid >> 5, lane = tid & 31;
    int wm = warp & 1, wn = warp >> 1;

    float acc[4][4];
    #pragma unroll
    for (int a = 0; a < 4; a++)
        #pragma unroll
        for (int b = 0; b < 4; b++) acc[a][b] = 0.f;

    #pragma unroll
    for (int ks = 0; ks < 8; ks++) {
        int k0 = ks * 8;
        int ar = wm * 16 + (lane >> 2);
        int ac = k0 + (lane & 3);
        float af0 = sV[ar * 68 + ac];
        float af1 = sV[(ar + 8) * 68 + ac];
        float af2 = sV[ar * 68 + ac + 4];
        float af3 = sV[(ar + 8) * 68 + ac + 4];
        uint32_t a0, a1, a2, a3;
        asm volatile("cvt.rna.tf32.f32 %0,%1;\n" : "=r"(a0) : "f"(af0));
        asm volatile("cvt.rna.tf32.f32 %0,%1;\n" : "=r"(a1) : "f"(af1));
        asm volatile("cvt.rna.tf32.f32 %0,%1;\n" : "=r"(a2) : "f"(af2));
        asm volatile("cvt.rna.tf32.f32 %0,%1;\n" : "=r"(a3) : "f"(af3));
        #pragma unroll
        for (int nt = 0; nt < 4; nt++) {
            int n0 = wn * 32 + nt * 8 + (lane >> 2);
            float bf0 = sW[n0 * 68 + k0 + (lane & 3)];
            float bf1 = sW[n0 * 68 + k0 + 4 + (lane & 3)];
            uint32_t b0, b1;
            asm volatile("cvt.rna.tf32.f32 %0,%1;\n" : "=r"(b0) : "f"(bf0));
            asm volatile("cvt.rna.tf32.f32 %0,%1;\n" : "=r"(b1) : "f"(bf1));
            asm volatile(
                "mma.sync.aligned.m16n8k8.row.col.f32.tf32.tf32.f32 "
                "{%0,%1,%2,%3},{%4,%5,%6,%7},{%8,%9},{%0,%1,%2,%3};\n"
                : "+f"(acc[nt][0]), "+f"(acc[nt][1]), "+f"(acc[nt][2]), "+f"(acc[nt][3])
                : "r"(a0), "r"(a1), "r"(a2), "r"(a3), "r"(b0), "r"(b1));
        }
    }

    #pragma unroll
    for (int nt = 0; nt < 4; nt++) {
        int gr = r0 + wm * 16 + (lane >> 2);
        int h  = wn * 32 + nt * 8 + (lane & 3) * 2;
        out[(size_t)gr * HH + h]           = 1.0f / (1.0f + __expf(-acc[nt][0]));
        out[(size_t)gr * HH + h + 1]       = 1.0f / (1.0f + __expf(-acc[nt][1]));
        out[(size_t)(gr + 8) * HH + h]     = 1.0f / (1.0f + __expf(-acc[nt][2]));
        out[(size_t)(gr + 8) * HH + h + 1] = 1.0f / (1.0f + __expf(-acc[nt][3]));
    }
}

// ---------------------------------------------------------------------------
// K5: copy A into second output slot
// ---------------------------------------------------------------------------
__global__ void copyA_kernel(const float* __restrict__ A, float* __restrict__ dst) {
    size_t i  = (size_t)blockIdx.x * blockDim.x + threadIdx.x;
    size_t n4 = (size_t)NN * NN / 4;
    const float4* src = reinterpret_cast<const float4*>(A);
    float4* d = reinterpret_cast<float4*>(dst);
    for (; i < n4; i += (size_t)gridDim.x * blockDim.x) d[i] = src[i];
}

// ---------------------------------------------------------------------------
extern "C" void kernel_launch(void* const* d_in, const int* in_sizes, int n_in,
                              void* d_out, int out_size) {
    const float* x = (const float*)d_in[0];   // [4,12,4096,64]
    const float* A = (const float*)d_in[1];   // [4096,4096]
    const float* W = (const float*)d_in[2];   // [128,64]
    float* out = (float*)d_out;               // out [48*4096*128] then A [4096*4096]

    rowsum_kernel<<<NN, 256>>>(A);
    convA_kernel<<<4096, 256>>>(A);
    build_xdt_kernel<<<dim3(NN / 64, BSDIM), 256>>>(x);
    gemm_bf16_kernel<<<dim3(NCOL / 128, NN / 128), 256>>>();
    epilogue_kernel<<<(BSDIM * NN) / 32, 256>>>(x, W, out);
    copyA_kernel<<<2048, 256>>>(A, out + (size_t)BSDIM * NN * HH);
}

// round 5
// speedup vs baseline: 8.5914x; 1.1540x over previous
#include <cuda_runtime.h>
#include <cuda_bf16.h>
#include <cstdint>

#define NN    4096
#define CC    64
#define HH    128
#define BSDIM 48
#define NCOL  (BSDIM * CC)    // 3072

// ---------------- scratch (__device__ globals; allocation-free) -------------
__device__ float         g_d[NN];
__device__ __nv_bfloat16 g_Abf[(size_t)NN * NN];       // 33.5 MB
__device__ __nv_bfloat16 g_XdT[(size_t)NCOL * NN];     // 25 MB  [col][j], K-major
__device__ float         g_U[(size_t)NN * NCOL];       // 50 MB  [i][col]

// ---------------------------------------------------------------------------
// K1 (fused): one pass over A -> rowsum/d, bf16 convert, copy to out slot 2
// ---------------------------------------------------------------------------
__global__ __launch_bounds__(256) void fuseA_kernel(const float* __restrict__ A,
                                                    float* __restrict__ Adst) {
    int row = blockIdx.x, tid = threadIdx.x;
    const float4* src = reinterpret_cast<const float4*>(A + (size_t)row * NN);
    float4* dst = reinterpret_cast<float4*>(Adst + (size_t)row * NN);
    __nv_bfloat162* ob = reinterpret_cast<__nv_bfloat162*>(g_Abf + (size_t)row * NN);
    float s = 0.f;
    #pragma unroll
    for (int it = 0; it < 4; it++) {
        int i = tid + it * 256;
        float4 v = src[i];
        dst[i] = v;
        ob[2 * i]     = __floats2bfloat162_rn(v.x, v.y);
        ob[2 * i + 1] = __floats2bfloat162_rn(v.z, v.w);
        s += (v.x + v.y) + (v.z + v.w);
    }
    __shared__ float red[8];
    #pragma unroll
    for (int o = 16; o > 0; o >>= 1) s += __shfl_down_sync(0xffffffffu, s, o);
    if ((tid & 31) == 0) red[tid >> 5] = s;
    __syncthreads();
    if (tid < 8) {
        float v = red[tid];
        #pragma unroll
        for (int o = 4; o > 0; o >>= 1) v += __shfl_down_sync(0xffu, v, o);
        if (tid == 0) g_d[row] = rsqrtf(v + 1.0f);
    }
}

// ---------------------------------------------------------------------------
// K2: XdT[bs*64+c][j] = bf16(d_j * x[bs,j,c])
// ---------------------------------------------------------------------------
__global__ __launch_bounds__(256) void build_xdt_kernel(const float* __restrict__ x) {
    __shared__ float ts[64 * 65];
    int bs = blockIdx.y, j0 = blockIdx.x * 64, tid = threadIdx.x;
    const float* xb = x + ((size_t)bs * NN + j0) * CC;
    for (int idx = tid; idx < 64 * CC; idx += 256)
        ts[(idx >> 6) * 65 + (idx & 63)] = xb[idx];
    __syncthreads();
    for (int idx = tid; idx < 64 * CC; idx += 256) {
        int c = idx >> 6, jj = idx & 63;
        int j = j0 + jj;
        g_XdT[((size_t)bs * CC + c) * NN + j] = __float2bfloat16(g_d[j] * ts[jj * 65 + c]);
    }
}

// ---------------------------------------------------------------------------
// K3: U = Abf @ XdT^T  (bf16 mma.sync, fp32 accum)
// CTA 128x256, BK=64, 3-stage cp.async, 8 warps, warp tile 64x64
// grid = (NCOL/256=12, NN/128=32) = 384
// ---------------------------------------------------------------------------
#define GS      3
#define BKG     64
#define KTI     (NN / BKG)       // 64
#define ASTRIDE 72               // 64 + 8 pad (bf16 elems)
#define A_SZ    (128 * ASTRIDE)  // elems per stage
#define B_SZ    (256 * ASTRIDE)
#define SMEM_GEMM (GS * (A_SZ + B_SZ) * 2)   // 165888 B

__global__ __launch_bounds__(256, 1) void gemm_bf16_kernel() {
    extern __shared__ __nv_bfloat16 smg[];
    uint32_t saA = (uint32_t)__cvta_generic_to_shared(smg);
    uint32_t saB = saA + GS * A_SZ * 2;

    int tid = threadIdx.x, warp = tid >> 5, lane = tid & 31;
    int rowBase = blockIdx.y * 128;
    int colBase = blockIdx.x * 256;
    int wm = warp & 1;            // M half (64 rows)
    int wn = warp >> 1;           // N quarter (64 cols)

    float acc[4][8][4];
    #pragma unroll
    for (int a = 0; a < 4; a++)
        #pragma unroll
        for (int b = 0; b < 8; b++)
            #pragma unroll
            for (int c = 0; c < 4; c++) acc[a][b][c] = 0.f;

    auto load_stage = [&](int s, int kt) {
        int k0 = kt * BKG;
        #pragma unroll
        for (int it = 0; it < 4; it++) {          // A: 128 rows x 8 chunks
            int lin = tid + it * 256;
            int r = lin >> 3, ch = lin & 7;
            const __nv_bfloat16* src = g_Abf + (size_t)(rowBase + r) * NN + k0 + ch * 8;
            uint32_t dst = saA + (s * A_SZ + r * ASTRIDE + ch * 8) * 2;
            asm volatile("cp.async.cg.shared.global [%0],[%1],16;" :: "r"(dst), "l"(src));
        }
        #pragma unroll
        for (int it = 0; it < 8; it++) {          // B: 256 rows x 8 chunks
            int lin = tid + it * 256;
            int r = lin >> 3, ch = lin & 7;
            const __nv_bfloat16* src = g_XdT + (size_t)(colBase + r) * NN + k0 + ch * 8;
            uint32_t dst = saB + (s * B_SZ + r * ASTRIDE + ch * 8) * 2;
            asm volatile("cp.async.cg.shared.global [%0],[%1],16;" :: "r"(dst), "l"(src));
        }
        asm volatile("cp.async.commit_group;" ::);
    };

    // prologue: stages 0,1
    load_stage(0, 0);
    load_stage(1, 1);

    int s = 0;
    for (int kt = 0; kt < KTI; kt++) {
        asm volatile("cp.async.wait_group 1;" ::);
        __syncthreads();

        // issue next loads (into slot that was consumed at kt-1)
        int ls = s + 2; if (ls >= GS) ls -= GS;
        if (kt + 2 < KTI) load_stage(ls, kt + 2);
        else asm volatile("cp.async.commit_group;" ::);   // keep group count invariant

        // compute stage s
        uint32_t baseA = saA + s * A_SZ * 2;
        uint32_t baseB = saB + s * B_SZ * 2;
        #pragma unroll
        for (int kk = 0; kk < 4; kk++) {
            uint32_t a[4][4], b[4][4];
            #pragma unroll
            for (int mi = 0; mi < 4; mi++) {
                uint32_t addr = baseA +
                    ((wm * 64 + mi * 16 + (lane & 15)) * ASTRIDE + kk * 16 + (lane >> 4) * 8) * 2;
                asm volatile("ldmatrix.sync.aligned.m8n8.x4.shared.b16 {%0,%1,%2,%3},[%4];"
                    : "=r"(a[mi][0]), "=r"(a[mi][1]), "=r"(a[mi][2]), "=r"(a[mi][3]) : "r"(addr));
            }
            #pragma unroll
            for (int nj = 0; nj < 4; nj++) {
                uint32_t addr = baseB +
                    ((wn * 64 + nj * 16 + (lane & 15)) * ASTRIDE + kk * 16 + (lane >> 4) * 8) * 2;
                asm volatile("ldmatrix.sync.aligned.m8n8.x4.shared.b16 {%0,%1,%2,%3},[%4];"
                    : "=r"(b[nj][0]), "=r"(b[nj][1]), "=r"(b[nj][2]), "=r"(b[nj][3]) : "r"(addr));
            }
            #pragma unroll
            for (int mi = 0; mi < 4; mi++) {
                #pragma unroll
                for (int nj = 0; nj < 4; nj++) {
                    asm volatile(
                        "mma.sync.aligned.m16n8k16.row.col.f32.bf16.bf16.f32 "
                        "{%0,%1,%2,%3},{%4,%5,%6,%7},{%8,%9},{%0,%1,%2,%3};"
                        : "+f"(acc[mi][nj*2][0]), "+f"(acc[mi][nj*2][1]),
                          "+f"(acc[mi][nj*2][2]), "+f"(acc[mi][nj*2][3])
                        : "r"(a[mi][0]), "r"(a[mi][1]), "r"(a[mi][2]), "r"(a[mi][3]),
                          "r"(b[nj][0]), "r"(b[nj][2]));
                    asm volatile(
                        "mma.sync.aligned.m16n8k16.row.col.f32.bf16.bf16.f32 "
                        "{%0,%1,%2,%3},{%4,%5,%6,%7},{%8,%9},{%0,%1,%2,%3};"
                        : "+f"(acc[mi][nj*2+1][0]), "+f"(acc[mi][nj*2+1][1]),
                          "+f"(acc[mi][nj*2+1][2]), "+f"(acc[mi][nj*2+1][3])
                        : "r"(a[mi][0]), "r"(a[mi][1]), "r"(a[mi][2]), "r"(a[mi][3]),
                          "r"(b[nj][1]), "r"(b[nj][3]));
                }
            }
        }
        s = s + 1 == GS ? 0 : s + 1;
    }

    // store U (fp32)
    #pragma unroll
    for (int mi = 0; mi < 4; mi++) {
        int r0 = rowBase + wm * 64 + mi * 16 + (lane >> 2);
        #pragma unroll
        for (int nf = 0; nf < 8; nf++) {
            int c = colBase + wn * 64 + nf * 8 + (lane & 3) * 2;
            *reinterpret_cast<float2*>(&g_U[(size_t)r0 * NCOL + c]) =
                make_float2(acc[mi][nf][0], acc[mi][nf][1]);
            *reinterpret_cast<float2*>(&g_U[(size_t)(r0 + 8) * NCOL + c]) =
                make_float2(acc[mi][nf][2], acc[mi][nf][3]);
        }
    }
}

// ---------------------------------------------------------------------------
// K4: out = sigmoid( (x - d*U) @ W^T )  via tf32 mma m16n8k8
// ---------------------------------------------------------------------------
__global__ __launch_bounds__(256) void epilogue_kernel(const float* __restrict__ x,
                                                       const float* __restrict__ W,
                                                       float* __restrict__ out) {
    __shared__ float sW[HH * 68];
    __shared__ float sV[32 * 68];
    int tid = threadIdx.x;
    int r0  = blockIdx.x * 32;
    int bs  = r0 >> 12;

    for (int idx = tid; idx < HH * CC; idx += 256) {
        int h = idx >> 6, c = idx & 63;
        sW[h * 68 + c] = W[idx];
    }
    for (int idx = tid; idx < 32 * CC; idx += 256) {
        int lr = idx >> 6, c = idx & 63;
        int gr = r0 + lr;
        int i  = gr & (NN - 1);
        sV[lr * 68 + c] = x[(size_t)gr * CC + c]
                        - g_d[i] * g_U[(size_t)i * NCOL + bs * CC + c];
    }
    __syncthreads();

    int warp = tid >> 5, lane = tid & 31;
    int wm = warp & 1, wn = warp >> 1;

    float acc[4][4];
    #pragma unroll
    for (int a = 0; a < 4; a++)
        #pragma unroll
        for (int b = 0; b < 4; b++) acc[a][b] = 0.f;

    #pragma unroll
    for (int ks = 0; ks < 8; ks++) {
        int k0 = ks * 8;
        int ar = wm * 16 + (lane >> 2);
        int ac = k0 + (lane & 3);
        float af0 = sV[ar * 68 + ac];
        float af1 = sV[(ar + 8) * 68 + ac];
        float af2 = sV[ar * 68 + ac + 4];
        float af3 = sV[(ar + 8) * 68 + ac + 4];
        uint32_t a0, a1, a2, a3;
        asm volatile("cvt.rna.tf32.f32 %0,%1;\n" : "=r"(a0) : "f"(af0));
        asm volatile("cvt.rna.tf32.f32 %0,%1;\n" : "=r"(a1) : "f"(af1));
        asm volatile("cvt.rna.tf32.f32 %0,%1;\n" : "=r"(a2) : "f"(af2));
        asm volatile("cvt.rna.tf32.f32 %0,%1;\n" : "=r"(a3) : "f"(af3));
        #pragma unroll
        for (int nt = 0; nt < 4; nt++) {
            int n0 = wn * 32 + nt * 8 + (lane >> 2);
            float bf0 = sW[n0 * 68 + k0 + (lane & 3)];
            float bf1 = sW[n0 * 68 + k0 + 4 + (lane & 3)];
            uint32_t b0, b1;
            asm volatile("cvt.rna.tf32.f32 %0,%1;\n" : "=r"(b0) : "f"(bf0));
            asm volatile("cvt.rna.tf32.f32 %0,%1;\n" : "=r"(b1) : "f"(bf1));
            asm volatile(
                "mma.sync.aligned.m16n8k8.row.col.f32.tf32.tf32.f32 "
                "{%0,%1,%2,%3},{%4,%5,%6,%7},{%8,%9},{%0,%1,%2,%3};\n"
                : "+f"(acc[nt][0]), "+f"(acc[nt][1]), "+f"(acc[nt][2]), "+f"(acc[nt][3])
                : "r"(a0), "r"(a1), "r"(a2), "r"(a3), "r"(b0), "r"(b1));
        }
    }

    #pragma unroll
    for (int nt = 0; nt < 4; nt++) {
        int gr = r0 + wm * 16 + (lane >> 2);
        int h  = wn * 32 + nt * 8 + (lane & 3) * 2;
        out[(size_t)gr * HH + h]           = 1.0f / (1.0f + __expf(-acc[nt][0]));
        out[(size_t)gr * HH + h + 1]       = 1.0f / (1.0f + __expf(-acc[nt][1]));
        out[(size_t)(gr + 8) * HH + h]     = 1.0f / (1.0f + __expf(-acc[nt][2]));
        out[(size_t)(gr + 8) * HH + h + 1] = 1.0f / (1.0f + __expf(-acc[nt][3]));
    }
}

// ---------------------------------------------------------------------------
extern "C" void kernel_launch(void* const* d_in, const int* in_sizes, int n_in,
                              void* d_out, int out_size) {
    const float* x = (const float*)d_in[0];   // [4,12,4096,64]
    const float* A = (const float*)d_in[1];   // [4096,4096]
    const float* W = (const float*)d_in[2];   // [128,64]
    float* out = (float*)d_out;               // out [48*4096*128] then A [4096*4096]

    cudaFuncSetAttribute(gemm_bf16_kernel,
                         cudaFuncAttributeMaxDynamicSharedMemorySize, SMEM_GEMM);

    fuseA_kernel<<<NN, 256>>>(A, out + (size_t)BSDIM * NN * HH);
    build_xdt_kernel<<<dim3(NN / 64, BSDIM), 256>>>(x);
    gemm_bf16_kernel<<<dim3(NCOL / 256, NN / 128), 256, SMEM_GEMM>>>();
    epilogue_kernel<<<(BSDIM * NN) / 32, 256>>>(x, W, out);
}

// round 7
// speedup vs baseline: 9.4337x; 1.0980x over previous
#include <cuda_runtime.h>
#include <cuda_bf16.h>
#include <cstdint>

#define NN    4096
#define CC    64
#define HH    128
#define BSDIM 48
#define NCOL  (BSDIM * CC)    // 3072

// ---------------- scratch (__device__ globals; allocation-free) -------------
__device__ float         g_d[NN];
__device__ __nv_bfloat16 g_Abf[(size_t)NN * NN];       // 33.5 MB
__device__ __nv_bfloat16 g_XdT[(size_t)NCOL * NN];     // 25 MB  [col][j], K-major
__device__ float         g_U[(size_t)NN * NCOL];       // 50 MB  [i][col]

// ---------------------------------------------------------------------------
// K1 (fused): one pass over A -> rowsum/d, bf16 convert, copy to out slot 2
// ---------------------------------------------------------------------------
__global__ __launch_bounds__(256) void fuseA_kernel(const float* __restrict__ A,
                                                    float* __restrict__ Adst) {
    int row = blockIdx.x, tid = threadIdx.x;
    const float4* src = reinterpret_cast<const float4*>(A + (size_t)row * NN);
    float4* dst = reinterpret_cast<float4*>(Adst + (size_t)row * NN);
    __nv_bfloat162* ob = reinterpret_cast<__nv_bfloat162*>(g_Abf + (size_t)row * NN);
    float s = 0.f;
    #pragma unroll
    for (int it = 0; it < 4; it++) {
        int i = tid + it * 256;
        float4 v = src[i];
        dst[i] = v;
        ob[2 * i]     = __floats2bfloat162_rn(v.x, v.y);
        ob[2 * i + 1] = __floats2bfloat162_rn(v.z, v.w);
        s += (v.x + v.y) + (v.z + v.w);
    }
    __shared__ float red[8];
    #pragma unroll
    for (int o = 16; o > 0; o >>= 1) s += __shfl_down_sync(0xffffffffu, s, o);
    if ((tid & 31) == 0) red[tid >> 5] = s;
    __syncthreads();
    if (tid < 8) {
        float v = red[tid];
        #pragma unroll
        for (int o = 4; o > 0; o >>= 1) v += __shfl_down_sync(0xffu, v, o);
        if (tid == 0) g_d[row] = rsqrtf(v + 1.0f);
    }
}

// ---------------------------------------------------------------------------
// K2: XdT[bs*64+c][j] = bf16(d_j * x[bs,j,c])
// ---------------------------------------------------------------------------
__global__ __launch_bounds__(256) void build_xdt_kernel(const float* __restrict__ x) {
    __shared__ float ts[64 * 65];
    int bs = blockIdx.y, j0 = blockIdx.x * 64, tid = threadIdx.x;
    const float* xb = x + ((size_t)bs * NN + j0) * CC;
    for (int idx = tid; idx < 64 * CC; idx += 256)
        ts[(idx >> 6) * 65 + (idx & 63)] = xb[idx];
    __syncthreads();
    for (int idx = tid; idx < 64 * CC; idx += 256) {
        int c = idx >> 6, jj = idx & 63;
        int j = j0 + jj;
        g_XdT[((size_t)bs * CC + c) * NN + j] = __float2bfloat16(g_d[j] * ts[jj * 65 + c]);
    }
}

// ---------------------------------------------------------------------------
// K3: U = Abf @ XdT^T  (bf16 mma.sync, fp32 accum)
// CTA 128x256, BK=64, 3-stage cp.async, 8 warps, warp tile 64x64,
// register double-buffered ldmatrix across kk
// grid = (NCOL/256=12, NN/128=32) = 384
// ---------------------------------------------------------------------------
#define GS      3
#define BKG     64
#define KTI     (NN / BKG)       // 64
#define ASTRIDE 72               // 64 + 8 pad (bf16 elems)
#define A_SZ    (128 * ASTRIDE)
#define B_SZ    (256 * ASTRIDE)
#define SMEM_GEMM (GS * (A_SZ + B_SZ) * 2)   // 165888 B

__global__ __launch_bounds__(256, 1) void gemm_bf16_kernel() {
    extern __shared__ __nv_bfloat16 smg[];
    uint32_t saA = (uint32_t)__cvta_generic_to_shared(smg);
    uint32_t saB = saA + GS * A_SZ * 2;

    int tid = threadIdx.x, warp = tid >> 5, lane = tid & 31;
    int rowBase = blockIdx.y * 128;
    int colBase = blockIdx.x * 256;
    int wm = warp & 1;            // M half (64 rows)
    int wn = warp >> 1;           // N quarter (64 cols)

    float acc[4][8][4];
    #pragma unroll
    for (int a = 0; a < 4; a++)
        #pragma unroll
        for (int b = 0; b < 8; b++)
            #pragma unroll
            for (int c = 0; c < 4; c++) acc[a][b][c] = 0.f;

    auto load_stage = [&](int s, int kt) {
        int k0 = kt * BKG;
        #pragma unroll
        for (int it = 0; it < 4; it++) {          // A: 128 rows x 8 chunks
            int lin = tid + it * 256;
            int r = lin >> 3, ch = lin & 7;
            const __nv_bfloat16* src = g_Abf + (size_t)(rowBase + r) * NN + k0 + ch * 8;
            uint32_t dst = saA + (s * A_SZ + r * ASTRIDE + ch * 8) * 2;
            asm volatile("cp.async.cg.shared.global [%0],[%1],16;" :: "r"(dst), "l"(src));
        }
        #pragma unroll
        for (int it = 0; it < 8; it++) {          // B: 256 rows x 8 chunks
            int lin = tid + it * 256;
            int r = lin >> 3, ch = lin & 7;
            const __nv_bfloat16* src = g_XdT + (size_t)(colBase + r) * NN + k0 + ch * 8;
            uint32_t dst = saB + (s * B_SZ + r * ASTRIDE + ch * 8) * 2;
            asm volatile("cp.async.cg.shared.global [%0],[%1],16;" :: "r"(dst), "l"(src));
        }
        asm volatile("cp.async.commit_group;" ::);
    };

    // prologue: stages 0,1
    load_stage(0, 0);
    load_stage(1, 1);

    uint32_t a[2][4][4], b[2][4][4];

    auto ldfrag = [&](int buf, uint32_t baseA, uint32_t baseB, int kk) {
        #pragma unroll
        for (int mi = 0; mi < 4; mi++) {
            uint32_t addr = baseA +
                ((wm * 64 + mi * 16 + (lane & 15)) * ASTRIDE + kk * 16 + (lane >> 4) * 8) * 2;
            asm volatile("ldmatrix.sync.aligned.m8n8.x4.shared.b16 {%0,%1,%2,%3},[%4];"
                : "=r"(a[buf][mi][0]), "=r"(a[buf][mi][1]),
                  "=r"(a[buf][mi][2]), "=r"(a[buf][mi][3]) : "r"(addr));
        }
        #pragma unroll
        for (int nj = 0; nj < 4; nj++) {
            uint32_t addr = baseB +
                ((wn * 64 + nj * 16 + (lane & 15)) * ASTRIDE + kk * 16 + (lane >> 4) * 8) * 2;
            asm volatile("ldmatrix.sync.aligned.m8n8.x4.shared.b16 {%0,%1,%2,%3},[%4];"
                : "=r"(b[buf][nj][0]), "=r"(b[buf][nj][1]),
                  "=r"(b[buf][nj][2]), "=r"(b[buf][nj][3]) : "r"(addr));
        }
    };

    int s = 0;
    for (int kt = 0; kt < KTI; kt++) {
        asm volatile("cp.async.wait_group 1;" ::);
        __syncthreads();

        int ls = s + 2; if (ls >= GS) ls -= GS;
        if (kt + 2 < KTI) load_stage(ls, kt + 2);
        else asm volatile("cp.async.commit_group;" ::);

        uint32_t baseA = saA + s * A_SZ * 2;
        uint32_t baseB = saB + s * B_SZ * 2;

        ldfrag(0, baseA, baseB, 0);
        #pragma unroll
        for (int kk = 0; kk < 4; kk++) {
            int cur = kk & 1;
            if (kk < 3) ldfrag(cur ^ 1, baseA, baseB, kk + 1);
            #pragma unroll
            for (int mi = 0; mi < 4; mi++) {
                #pragma unroll
                for (int nj = 0; nj < 4; nj++) {
                    asm volatile(
                        "mma.sync.aligned.m16n8k16.row.col.f32.bf16.bf16.f32 "
                        "{%0,%1,%2,%3},{%4,%5,%6,%7},{%8,%9},{%0,%1,%2,%3};"
                        : "+f"(acc[mi][nj*2][0]), "+f"(acc[mi][nj*2][1]),
                          "+f"(acc[mi][nj*2][2]), "+f"(acc[mi][nj*2][3])
                        : "r"(a[cur][mi][0]), "r"(a[cur][mi][1]),
                          "r"(a[cur][mi][2]), "r"(a[cur][mi][3]),
                          "r"(b[cur][nj][0]), "r"(b[cur][nj][2]));
                    asm volatile(
                        "mma.sync.aligned.m16n8k16.row.col.f32.bf16.bf16.f32 "
                        "{%0,%1,%2,%3},{%4,%5,%6,%7},{%8,%9},{%0,%1,%2,%3};"
                        : "+f"(acc[mi][nj*2+1][0]), "+f"(acc[mi][nj*2+1][1]),
                          "+f"(acc[mi][nj*2+1][2]), "+f"(acc[mi][nj*2+1][3])
                        : "r"(a[cur][mi][0]), "r"(a[cur][mi][1]),
                          "r"(a[cur][mi][2]), "r"(a[cur][mi][3]),
                          "r"(b[cur][nj][1]), "r"(b[cur][nj][3]));
                }
            }
        }
        s = s + 1 == GS ? 0 : s + 1;
    }

    // store U (fp32)
    #pragma unroll
    for (int mi = 0; mi < 4; mi++) {
        int r0 = rowBase + wm * 64 + mi * 16 + (lane >> 2);
        #pragma unroll
        for (int nf = 0; nf < 8; nf++) {
            int c = colBase + wn * 64 + nf * 8 + (lane & 3) * 2;
            *reinterpret_cast<float2*>(&g_U[(size_t)r0 * NCOL + c]) =
                make_float2(acc[mi][nf][0], acc[mi][nf][1]);
            *reinterpret_cast<float2*>(&g_U[(size_t)(r0 + 8) * NCOL + c]) =
                make_float2(acc[mi][nf][2], acc[mi][nf][3]);
        }
    }
}

// ---------------------------------------------------------------------------
// K4: out = sigmoid( (x - d*U) @ W^T )  via tf32 mma m16n8k8
// Block: 128 rows x 128 h; V and W pre-converted to tf32 in smem once.
// 8 warps as 4M x 2N, warp tile 32 rows x 64 h.
// grid = BSDIM*NN/128 = 1536, dynamic smem 2*128*68*4 = 69632 B
// ---------------------------------------------------------------------------
#define EP_STR 68
#define SMEM_EPI (2 * 128 * EP_STR * 4)

__global__ __launch_bounds__(256) void epilogue_kernel(const float* __restrict__ x,
                                                       const float* __restrict__ W,
                                                       float* __restrict__ out) {
    extern __shared__ float sm[];
    float* sW = sm;                 // [128][68] tf32 bits
    float* sV = sm + 128 * EP_STR;  // [128][68] tf32 bits
    int tid = threadIdx.x;
    int r0  = blockIdx.x * 128;     // flattened (bs,i) row
    int bs  = r0 >> 12;             // 128 | 4096 -> never straddles

    // stage W (cvt to tf32 once)
    #pragma unroll
    for (int it = 0; it < 8; it++) {
        int lin = tid + it * 256;   // 0..2047 float4s
        int h = lin >> 4, c4 = (lin & 15) * 4;
        float4 w = *reinterpret_cast<const float4*>(&W[h * CC + c4]);
        uint32_t t0, t1, t2, t3;
        asm volatile("cvt.rna.tf32.f32 %0,%1;" : "=r"(t0) : "f"(w.x));
        asm volatile("cvt.rna.tf32.f32 %0,%1;" : "=r"(t1) : "f"(w.y));
        asm volatile("cvt.rna.tf32.f32 %0,%1;" : "=r"(t2) : "f"(w.z));
        asm volatile("cvt.rna.tf32.f32 %0,%1;" : "=r"(t3) : "f"(w.w));
        *reinterpret_cast<float4*>(&sW[h * EP_STR + c4]) =
            make_float4(__uint_as_float(t0), __uint_as_float(t1),
                        __uint_as_float(t2), __uint_as_float(t3));
    }
    // stage V = x - d*U (cvt to tf32 once)
    #pragma unroll
    for (int it = 0; it < 8; it++) {
        int lin = tid + it * 256;
        int lr = lin >> 4, c4 = (lin & 15) * 4;
        int gr = r0 + lr;
        int i  = gr & (NN - 1);
        float di = g_d[i];
        float4 xv = *reinterpret_cast<const float4*>(&x[(size_t)gr * CC + c4]);
        float4 uv = *reinterpret_cast<const float4*>(&g_U[(size_t)i * NCOL + bs * CC + c4]);
        float4 v = make_float4(xv.x - di * uv.x, xv.y - di * uv.y,
                               xv.z - di * uv.z, xv.w - di * uv.w);
        uint32_t t0, t1, t2, t3;
        asm volatile("cvt.rna.tf32.f32 %0,%1;" : "=r"(t0) : "f"(v.x));
        asm volatile("cvt.rna.tf32.f32 %0,%1;" : "=r"(t1) : "f"(v.y));
        asm volatile("cvt.rna.tf32.f32 %0,%1;" : "=r"(t2) : "f"(v.z));
        asm volatile("cvt.rna.tf32.f32 %0,%1;" : "=r"(t3) : "f"(v.w));
        *reinterpret_cast<float4*>(&sV[lr * EP_STR + c4]) =
            make_float4(__uint_as_float(t0), __uint_as_float(t1),
                        __uint_as_float(t2), __uint_as_float(t3));
    }
    __syncthreads();

    int warp = tid >> 5, lane = tid & 31;
    int wm = warp & 3;              // 4 M groups of 32 rows
    int wn = warp >> 2;             // 2 N halves of 64 cols

    float acc[2][8][4];
    #pragma unroll
    for (int a = 0; a < 2; a++)
        #pragma unroll
        for (int b = 0; b < 8; b++)
            #pragma unroll
            for (int c = 0; c < 4; c++) acc[a][b][c] = 0.f;

    #pragma unroll
    for (int ks = 0; ks < 8; ks++) {
        int k0 = ks * 8;
        uint32_t av[2][4];
        #pragma unroll
        for (int mi = 0; mi < 2; mi++) {
            int ar = wm * 32 + mi * 16 + (lane >> 2);
            int ac = k0 + (lane & 3);
            av[mi][0] = __float_as_uint(sV[ar * EP_STR + ac]);
            av[mi][1] = __float_as_uint(sV[(ar + 8) * EP_STR + ac]);
            av[mi][2] = __float_as_uint(sV[ar * EP_STR + ac + 4]);
            av[mi][3] = __float_as_uint(sV[(ar + 8) * EP_STR + ac + 4]);
        }
        #pragma unroll
        for (int nt = 0; nt < 8; nt++) {
            int n0 = wn * 64 + nt * 8 + (lane >> 2);
            uint32_t b0 = __float_as_uint(sW[n0 * EP_STR + k0 + (lane & 3)]);
            uint32_t b1 = __float_as_uint(sW[n0 * EP_STR + k0 + 4 + (lane & 3)]);
            #pragma unroll
            for (int mi = 0; mi < 2; mi++) {
                asm volatile(
                    "mma.sync.aligned.m16n8k8.row.col.f32.tf32.tf32.f32 "
                    "{%0,%1,%2,%3},{%4,%5,%6,%7},{%8,%9},{%0,%1,%2,%3};"
                    : "+f"(acc[mi][nt][0]), "+f"(acc[mi][nt][1]),
                      "+f"(acc[mi][nt][2]), "+f"(acc[mi][nt][3])
                    : "r"(av[mi][0]), "r"(av[mi][1]), "r"(av[mi][2]), "r"(av[mi][3]),
                      "r"(b0), "r"(b1));
            }
        }
    }

    #pragma unroll
    for (int mi = 0; mi < 2; mi++) {
        int gr = r0 + wm * 32 + mi * 16 + (lane >> 2);
        #pragma unroll
        for (int nt = 0; nt < 8; nt++) {
            int h = wn * 64 + nt * 8 + (lane & 3) * 2;
            *reinterpret_cast<float2*>(&out[(size_t)gr * HH + h]) =
                make_float2(1.0f / (1.0f + __expf(-acc[mi][nt][0])),
                            1.0f / (1.0f + __expf(-acc[mi][nt][1])));
            *reinterpret_cast<float2*>(&out[(size_t)(gr + 8) * HH + h]) =
                make_float2(1.0f / (1.0f + __expf(-acc[mi][nt][2])),
                            1.0f / (1.0f + __expf(-acc[mi][nt][3])));
        }
    }
}

// ---------------------------------------------------------------------------
extern "C" void kernel_launch(void* const* d_in, const int* in_sizes, int n_in,
                              void* d_out, int out_size) {
    const float* x = (const float*)d_in[0];   // [4,12,4096,64]
    const float* A = (const float*)d_in[1];   // [4096,4096]
    const float* W = (const float*)d_in[2];   // [128,64]
    float* out = (float*)d_out;               // out [48*4096*128] then A [4096*4096]

    cudaFuncSetAttribute(gemm_bf16_kernel,
                         cudaFuncAttributeMaxDynamicSharedMemorySize, SMEM_GEMM);
    cudaFuncSetAttribute(epilogue_kernel,
                         cudaFuncAttributeMaxDynamicSharedMemorySize, SMEM_EPI);

    fuseA_kernel<<<NN, 256>>>(A, out + (size_t)BSDIM * NN * HH);
    build_xdt_kernel<<<dim3(NN / 64, BSDIM), 256>>>(x);
    gemm_bf16_kernel<<<dim3(NCOL / 256, NN / 128), 256, SMEM_GEMM>>>();
    epilogue_kernel<<<(BSDIM * NN) / 128, 256, SMEM_EPI>>>(x, W, out);
}